// round 9
// baseline (speedup 1.0000x reference)
#include <cuda_runtime.h>
#include <cuda_fp16.h>
#include <cstdint>
#include <cstddef>

// Problem dims
static constexpr int B_ = 16;
static constexpr int S_ = 2048;
static constexpr int H_ = 1024;
static constexpr int M  = B_ * S_;   // 32768
static constexpr int N3 = 3 * H_;    // 3072
static constexpr int K  = H_;        // 1024
static constexpr int BH = B_ * H_;   // 16384 chains

// GEMM tiling: 128x128 block, 8 warps of 64x32, BK=64 (R8 measured-good)
static constexpr int BM = 128, BN = 128, BK = 64;
static constexpr int NK = K / BK;                 // 16
static constexpr int STAGES = 3;
static constexpr int RS = 72;                     // halves per smem row (144B, conflict-free)
static constexpr int A_HALVES = BM * RS;          // 9216
static constexpr int STAGE_HALVES = 2 * A_HALVES; // 18432
static constexpr int STAGE_BYTES  = STAGE_HALVES * 2;        // 36864
static constexpr int SMEM_TOTAL   = STAGES * STAGE_BYTES;    // 110592

// Scan chunking
static constexpr int SC = 8;
static constexpr int CT = S_ / SC;       // 256

// Scratch (__device__ globals: allocation-free rule)
__device__ __half g_Ah[(size_t)M * K];
__device__ __half g_Wh[(size_t)N3 * K];
__device__ __half g_zh[(size_t)M * H_];
__device__ __half g_fh[(size_t)M * H_];
__device__ __half g_oh[(size_t)M * H_];
__device__ float  g_cA[(size_t)BH * (SC - 1)];
__device__ float  g_cP[(size_t)BH * (SC - 1)];
__device__ float  g_hs[(size_t)BH * SC];

__device__ __forceinline__ float fsig(float x) {
    float e = __expf(-x);
    return __fdividef(1.0f, 1.0f + e);
}
__device__ __forceinline__ float ftanh(float x) {
    return fmaf(2.0f, fsig(2.0f * x), -1.0f);
}
__device__ __forceinline__ uint32_t smem_u32(const void* p) {
    uint32_t a;
    asm("{ .reg .u64 t; cvta.to.shared.u64 t, %1; cvt.u32.u64 %0, t; }" : "=r"(a) : "l"(p));
    return a;
}
__device__ __forceinline__ void cp_async16(uint32_t sa, const void* g) {
    asm volatile("cp.async.cg.shared.global [%0], [%1], 16;\n" :: "r"(sa), "l"(g));
}
__device__ __forceinline__ void ldmatrix_x4(uint32_t* r, uint32_t addr) {
    asm volatile("ldmatrix.sync.aligned.m8n8.x4.shared.b16 {%0,%1,%2,%3}, [%4];"
                 : "=r"(r[0]), "=r"(r[1]), "=r"(r[2]), "=r"(r[3]) : "r"(addr));
}
// NON-volatile: pure register dataflow; lets ptxas interleave with LDSM
__device__ __forceinline__ void mma16816(float* d, const uint32_t* a, const uint32_t* b) {
    asm("mma.sync.aligned.m16n8k16.row.col.f32.f16.f16.f32 "
        "{%0,%1,%2,%3}, {%4,%5,%6,%7}, {%8,%9}, {%0,%1,%2,%3};\n"
        : "+f"(d[0]), "+f"(d[1]), "+f"(d[2]), "+f"(d[3])
        : "r"(a[0]), "r"(a[1]), "r"(a[2]), "r"(a[3]), "r"(b[0]), "r"(b[1]));
}

__global__ void nop_a() {}

// ---------------------------------------------------------------------------
__global__ __launch_bounds__(256) void cvt_f2h(const float* __restrict__ src,
                                               __half* __restrict__ dst, int n)
{
    int i = (blockIdx.x * 256 + threadIdx.x) * 8;
    if (i >= n) return;
    float4 a = *(const float4*)(src + i);
    float4 b = *(const float4*)(src + i + 4);
    __half2 h0 = __floats2half2_rn(a.x, a.y);
    __half2 h1 = __floats2half2_rn(a.z, a.w);
    __half2 h2 = __floats2half2_rn(b.x, b.y);
    __half2 h3 = __floats2half2_rn(b.z, b.w);
    uint4 o;
    o.x = *(uint32_t*)&h0; o.y = *(uint32_t*)&h1;
    o.z = *(uint32_t*)&h2; o.w = *(uint32_t*)&h3;
    *(uint4*)(dst + i) = o;
}

// ---------------------------------------------------------------------------
// fp16 GEMM, 64x32 warp tiles, BK=64, hand-pipelined LDSM/MMA interleave.
// ---------------------------------------------------------------------------
__global__ __launch_bounds__(256) void qrnn_gemm_h(const float* __restrict__ bias)
{
    extern __shared__ char smem[];
    const int tid  = threadIdx.x;
    const int lane = tid & 31;
    const int wid  = tid >> 5;
    const int wm   = wid >> 2;        // 0..1 : 64 rows
    const int wn   = wid & 3;         // 0..3 : 32 cols
    const int m0 = blockIdx.y * BM;
    const int n0 = blockIdx.x * BN;
    const uint32_t sbase = smem_u32(smem);

    float acc[4][4][4];
    #pragma unroll
    for (int mi = 0; mi < 4; mi++)
        #pragma unroll
        for (int ni = 0; ni < 4; ni++)
            #pragma unroll
            for (int r = 0; r < 4; r++) acc[mi][ni][r] = 0.0f;

    auto load_stage = [&](int kt, int buf) {
        const int k0 = kt * BK;
        const uint32_t st = sbase + buf * STAGE_BYTES;
        #pragma unroll
        for (int i = 0; i < 8; i++) {
            int id  = tid + i * 256;         // 0..2047
            int isB = id >> 10;
            int loc = id & 1023;
            int r   = loc >> 3;
            int ch  = loc & 7;
            uint32_t dstofs = (uint32_t)(isB * A_HALVES + r * RS + ch * 8) * 2;
            const __half* gp = isB
                ? (g_Wh + (size_t)(n0 + r) * K + k0 + ch * 8)
                : (g_Ah + (size_t)(m0 + r) * K + k0 + ch * 8);
            cp_async16(st + dstofs, gp);
        }
        asm volatile("cp.async.commit_group;\n" ::: "memory");
    };

    load_stage(0, 0);
    load_stage(1, 1);

    // precomputed intra-warp frag offsets
    const int a_row = (lane & 7) + 8 * ((lane >> 3) & 1);
    const int a_kof = 8 * (lane >> 4);
    const int b_row = (lane & 7) + 8 * (lane >> 4);
    const int b_kof = 8 * ((lane >> 3) & 1);

    for (int kt = 0; kt < NK; kt++) {
        if (kt + STAGES - 1 < NK) load_stage(kt + STAGES - 1, (kt + STAGES - 1) % STAGES);
        if (kt < NK - 1) asm volatile("cp.async.wait_group 1;\n" ::: "memory");
        else             asm volatile("cp.async.wait_group 0;\n" ::: "memory");
        __syncthreads();

        const uint32_t aB = sbase + (kt % STAGES) * STAGE_BYTES;
        const uint32_t bB = aB + A_HALVES * 2;

        #pragma unroll
        for (int ks = 0; ks < 4; ks++) {
            uint32_t afr[4][4], bfr[4][2];
            // B frags first (needed by every MMA)
            #pragma unroll
            for (int nb = 0; nb < 2; nb++) {
                int row = wn * 32 + nb * 16 + b_row;
                uint32_t t[4];
                ldmatrix_x4(t, bB + (uint32_t)(row * RS + ks * 16 + b_kof) * 2);
                bfr[nb * 2][0] = t[0]; bfr[nb * 2][1] = t[1];
                bfr[nb * 2 + 1][0] = t[2]; bfr[nb * 2 + 1][1] = t[3];
            }
            // A[0], then interleave: load A[mi+1] before MMAs of A[mi]
            ldmatrix_x4(afr[0], aB + (uint32_t)((wm * 64 + a_row) * RS + ks * 16 + a_kof) * 2);
            #pragma unroll
            for (int mi = 0; mi < 4; mi++) {
                if (mi < 3) {
                    int row = wm * 64 + (mi + 1) * 16 + a_row;
                    ldmatrix_x4(afr[mi + 1], aB + (uint32_t)(row * RS + ks * 16 + a_kof) * 2);
                }
                #pragma unroll
                for (int ni = 0; ni < 4; ni++)
                    mma16816(acc[mi][ni], afr[mi], bfr[ni]);
            }
        }
        __syncthreads();
    }

    // epilogue: bias + activation -> fp16 gate arrays
    const int gate  = n0 >> 10;
    const int hbase = n0 & (H_ - 1);
    __half* dst = (gate == 0) ? g_zh : ((gate == 1) ? g_fh : g_oh);

    #pragma unroll
    for (int mi = 0; mi < 4; mi++) {
        int r0 = m0 + wm * 64 + mi * 16 + (lane >> 2);
        #pragma unroll
        for (int ni = 0; ni < 4; ni++) {
            int c  = wn * 32 + ni * 8 + (lane & 3) * 2;
            float bx = __ldg(&bias[n0 + c]);
            float by = __ldg(&bias[n0 + c + 1]);
            float v0 = acc[mi][ni][0] + bx, v1 = acc[mi][ni][1] + by;
            float v2 = acc[mi][ni][2] + bx, v3 = acc[mi][ni][3] + by;
            if (gate == 0) { v0 = ftanh(v0); v1 = ftanh(v1); v2 = ftanh(v2); v3 = ftanh(v3); }
            else           { v0 = fsig(v0);  v1 = fsig(v1);  v2 = fsig(v2);  v3 = fsig(v3); }
            __half2 lo = __floats2half2_rn(v0, v1);
            __half2 hi = __floats2half2_rn(v2, v3);
            *(__half2*)&dst[(size_t)r0 * H_ + hbase + c]       = lo;
            *(__half2*)&dst[(size_t)(r0 + 8) * H_ + hbase + c] = hi;
        }
    }
}

// ---------------------------------------------------------------------------
// Chunked scan — R5 scalar version (measured best).
// ---------------------------------------------------------------------------
__global__ __launch_bounds__(256) void scan_p1()
{
    const int idx   = blockIdx.x * 256 + threadIdx.x;   // over (SC-1)*BH
    const int chain = idx & (BH - 1);
    const int c     = idx >> 14;
    const int b = chain >> 10, h = chain & (H_ - 1);
    const size_t base = ((size_t)b * S_ + (size_t)c * CT) * H_ + h;

    constexpr int U = 8;
    float z[U], f[U];
    #pragma unroll
    for (int j = 0; j < U; j++) {
        size_t p = base + (size_t)j * H_;
        z[j] = __half2float(g_zh[p]); f[j] = __half2float(g_fh[p]);
    }
    float hh = 0.0f, P = 1.0f;
    for (int t = 0; t < CT; t += U) {
        float zn[U], fn[U];
        if (t + U < CT) {
            #pragma unroll
            for (int j = 0; j < U; j++) {
                size_t p = base + (size_t)(t + U + j) * H_;
                zn[j] = __half2float(g_zh[p]); fn[j] = __half2float(g_fh[p]);
            }
        }
        #pragma unroll
        for (int j = 0; j < U; j++) {
            hh = fmaf(f[j], z[j] - hh, hh);
            P *= (1.0f - f[j]);
        }
        #pragma unroll
        for (int j = 0; j < U; j++) { z[j] = zn[j]; f[j] = fn[j]; }
    }
    g_cA[idx] = hh;
    g_cP[idx] = P;
}

__global__ __launch_bounds__(256) void scan_p2()
{
    const int chain = blockIdx.x * 256 + threadIdx.x;
    float hs = 0.0f;
    g_hs[chain] = 0.0f;
    #pragma unroll
    for (int c = 0; c < SC - 1; c++) {
        hs = fmaf(g_cP[c * BH + chain], hs, g_cA[c * BH + chain]);
        g_hs[(c + 1) * BH + chain] = hs;
    }
}

__global__ __launch_bounds__(256) void scan_p3(float* __restrict__ out, int write_clast)
{
    const int idx   = blockIdx.x * 256 + threadIdx.x;   // over SC*BH
    const int chain = idx & (BH - 1);
    const int c     = idx >> 14;
    const int b = chain >> 10, h = chain & (H_ - 1);
    const size_t base = ((size_t)b * S_ + (size_t)c * CT) * H_ + h;

    constexpr int U = 8;
    float z[U], f[U], o[U];
    #pragma unroll
    for (int j = 0; j < U; j++) {
        size_t p = base + (size_t)j * H_;
        z[j] = __half2float(g_zh[p]); f[j] = __half2float(g_fh[p]);
        o[j] = __half2float(g_oh[p]);
    }
    float hh = g_hs[idx];
    for (int t = 0; t < CT; t += U) {
        float zn[U], fn[U], on[U];
        if (t + U < CT) {
            #pragma unroll
            for (int j = 0; j < U; j++) {
                size_t p = base + (size_t)(t + U + j) * H_;
                zn[j] = __half2float(g_zh[p]); fn[j] = __half2float(g_fh[p]);
                on[j] = __half2float(g_oh[p]);
            }
        }
        #pragma unroll
        for (int j = 0; j < U; j++) {
            hh = fmaf(f[j], z[j] - hh, hh);
            out[base + (size_t)(t + j) * H_] = o[j] * hh;
        }
        #pragma unroll
        for (int j = 0; j < U; j++) { z[j] = zn[j]; f[j] = fn[j]; o[j] = on[j]; }
    }
    if (write_clast && c == SC - 1)
        out[(size_t)M * H_ + chain] = hh;
}

// ---------------------------------------------------------------------------
extern "C" void kernel_launch(void* const* d_in, const int* in_sizes, int n_in,
                              void* d_out, int out_size)
{
    const float* inp  = (const float*)d_in[0];
    const float* Wt   = (const float*)d_in[1];
    const float* bias = (const float*)d_in[2];
    float* out = (float*)d_out;

    {
        int nA = M * K, nW = N3 * K;
        __half* dA; __half* dW;
        cudaGetSymbolAddress((void**)&dA, g_Ah);
        cudaGetSymbolAddress((void**)&dW, g_Wh);
        cvt_f2h<<<(nA / 8 + 255) / 256, 256>>>(inp, dA, nA);   // idx 0
        cvt_f2h<<<(nW / 8 + 255) / 256, 256>>>(Wt, dW, nW);    // idx 1
    }

    nop_a<<<1, 32>>>();                                        // idx 2

    // idx 3 == profiler capture slot
    cudaFuncSetAttribute(qrnn_gemm_h, cudaFuncAttributeMaxDynamicSharedMemorySize, SMEM_TOTAL);
    dim3 grid(N3 / BN, M / BM);                                // 24 x 256
    qrnn_gemm_h<<<grid, 256, SMEM_TOTAL>>>(bias);              // idx 3

    const long long need = (long long)M * H_ + (long long)BH;
    int write_clast = ((long long)out_size >= need) ? 1 : 0;

    scan_p1<<<(SC - 1) * BH / 256, 256>>>();                   // idx 4
    scan_p2<<<BH / 256, 256>>>();                              // idx 5
    scan_p3<<<SC * BH / 256, 256>>>(out, write_clast);         // idx 6
}

// round 10
// speedup vs baseline: 1.4724x; 1.4724x over previous
#include <cuda_runtime.h>
#include <cuda_fp16.h>
#include <cstdint>
#include <cstddef>

// Problem dims
static constexpr int B_ = 16;
static constexpr int S_ = 2048;
static constexpr int H_ = 1024;
static constexpr int M  = B_ * S_;   // 32768
static constexpr int N3 = 3 * H_;    // 3072
static constexpr int K  = H_;        // 1024
static constexpr int BH = B_ * H_;   // 16384 chains

// GEMM tiling: 128x128 block, 8 warps of 64x32, BK=64 (R8 measured-good)
static constexpr int BM = 128, BN = 128, BK = 64;
static constexpr int NK = K / BK;                 // 16
static constexpr int STAGES = 3;
static constexpr int RS = 72;                     // halves per smem row (144B, conflict-free)
static constexpr int A_HALVES = BM * RS;          // 9216
static constexpr int STAGE_HALVES = 2 * A_HALVES; // 18432
static constexpr int STAGE_BYTES  = STAGE_HALVES * 2;        // 36864
static constexpr int SMEM_TOTAL   = STAGES * STAGE_BYTES;    // 110592

// Scan chunking (SC=16 for higher occupancy in latency-bound phases)
static constexpr int SC = 16;
static constexpr int CT = S_ / SC;       // 128

// Scratch (__device__ globals: allocation-free rule)
__device__ __half g_Ah[(size_t)M * K];
__device__ __half g_Wh[(size_t)N3 * K];
__device__ __half g_zh[(size_t)M * H_];
__device__ __half g_fh[(size_t)M * H_];
__device__ __half g_oh[(size_t)M * H_];
__device__ float  g_cA[(size_t)BH * (SC - 1)];
__device__ float  g_cP[(size_t)BH * (SC - 1)];
__device__ float  g_hs[(size_t)BH * SC];

__device__ __forceinline__ float fsig(float x) {
    float e = __expf(-x);
    return __fdividef(1.0f, 1.0f + e);
}
__device__ __forceinline__ float ftanh(float x) {
    return fmaf(2.0f, fsig(2.0f * x), -1.0f);
}
__device__ __forceinline__ uint32_t smem_u32(const void* p) {
    uint32_t a;
    asm("{ .reg .u64 t; cvta.to.shared.u64 t, %1; cvt.u32.u64 %0, t; }" : "=r"(a) : "l"(p));
    return a;
}
__device__ __forceinline__ void cp_async16(uint32_t sa, const void* g) {
    asm volatile("cp.async.cg.shared.global [%0], [%1], 16;\n" :: "r"(sa), "l"(g));
}
__device__ __forceinline__ void ldmatrix_x4(uint32_t* r, uint32_t addr) {
    asm volatile("ldmatrix.sync.aligned.m8n8.x4.shared.b16 {%0,%1,%2,%3}, [%4];"
                 : "=r"(r[0]), "=r"(r[1]), "=r"(r[2]), "=r"(r[3]) : "r"(addr));
}
__device__ __forceinline__ void mma16816(float* d, const uint32_t* a, const uint32_t* b) {
    asm volatile(
        "mma.sync.aligned.m16n8k16.row.col.f32.f16.f16.f32 "
        "{%0,%1,%2,%3}, {%4,%5,%6,%7}, {%8,%9}, {%0,%1,%2,%3};\n"
        : "+f"(d[0]), "+f"(d[1]), "+f"(d[2]), "+f"(d[3])
        : "r"(a[0]), "r"(a[1]), "r"(a[2]), "r"(a[3]), "r"(b[0]), "r"(b[1]));
}

__global__ void nop_a() {}

// ---------------------------------------------------------------------------
__global__ __launch_bounds__(256) void cvt_f2h(const float* __restrict__ src,
                                               __half* __restrict__ dst, int n)
{
    int i = (blockIdx.x * 256 + threadIdx.x) * 8;
    if (i >= n) return;
    float4 a = *(const float4*)(src + i);
    float4 b = *(const float4*)(src + i + 4);
    __half2 h0 = __floats2half2_rn(a.x, a.y);
    __half2 h1 = __floats2half2_rn(a.z, a.w);
    __half2 h2 = __floats2half2_rn(b.x, b.y);
    __half2 h3 = __floats2half2_rn(b.z, b.w);
    uint4 o;
    o.x = *(uint32_t*)&h0; o.y = *(uint32_t*)&h1;
    o.z = *(uint32_t*)&h2; o.w = *(uint32_t*)&h3;
    *(uint4*)(dst + i) = o;
}

// ---------------------------------------------------------------------------
// fp16 GEMM, R8 exact: 64x32 warp tiles, BK=64, batched LDSM then MMA.
// ---------------------------------------------------------------------------
__global__ __launch_bounds__(256) void qrnn_gemm_h(const float* __restrict__ bias)
{
    extern __shared__ char smem[];
    const int tid  = threadIdx.x;
    const int lane = tid & 31;
    const int wid  = tid >> 5;
    const int wm   = wid >> 2;        // 0..1 : 64 rows
    const int wn   = wid & 3;         // 0..3 : 32 cols
    const int m0 = blockIdx.y * BM;
    const int n0 = blockIdx.x * BN;
    const uint32_t sbase = smem_u32(smem);

    float acc[4][4][4];
    #pragma unroll
    for (int mi = 0; mi < 4; mi++)
        #pragma unroll
        for (int ni = 0; ni < 4; ni++)
            #pragma unroll
            for (int r = 0; r < 4; r++) acc[mi][ni][r] = 0.0f;

    auto load_stage = [&](int kt, int buf) {
        const int k0 = kt * BK;
        const uint32_t st = sbase + buf * STAGE_BYTES;
        #pragma unroll
        for (int i = 0; i < 8; i++) {
            int id  = tid + i * 256;         // 0..2047
            int isB = id >> 10;
            int loc = id & 1023;
            int r   = loc >> 3;
            int ch  = loc & 7;
            uint32_t dstofs = (uint32_t)(isB * A_HALVES + r * RS + ch * 8) * 2;
            const __half* gp = isB
                ? (g_Wh + (size_t)(n0 + r) * K + k0 + ch * 8)
                : (g_Ah + (size_t)(m0 + r) * K + k0 + ch * 8);
            cp_async16(st + dstofs, gp);
        }
        asm volatile("cp.async.commit_group;\n" ::: "memory");
    };

    load_stage(0, 0);
    load_stage(1, 1);

    for (int kt = 0; kt < NK; kt++) {
        if (kt + STAGES - 1 < NK) load_stage(kt + STAGES - 1, (kt + STAGES - 1) % STAGES);
        if (kt < NK - 1) asm volatile("cp.async.wait_group 1;\n" ::: "memory");
        else             asm volatile("cp.async.wait_group 0;\n" ::: "memory");
        __syncthreads();

        const uint32_t aB = sbase + (kt % STAGES) * STAGE_BYTES;
        const uint32_t bB = aB + A_HALVES * 2;

        #pragma unroll
        for (int ks = 0; ks < 4; ks++) {
            uint32_t afr[4][4], bfr[4][2];
            #pragma unroll
            for (int mi = 0; mi < 4; mi++) {
                int m   = wm * 64 + mi * 16;
                int row = m + (lane & 7) + 8 * ((lane >> 3) & 1);
                int kof = ks * 16 + 8 * (lane >> 4);
                ldmatrix_x4(afr[mi], aB + (uint32_t)(row * RS + kof) * 2);
            }
            #pragma unroll
            for (int nb = 0; nb < 2; nb++) {
                int n   = wn * 32 + nb * 16;
                int row = n + (lane & 7) + 8 * (lane >> 4);
                int kof = ks * 16 + 8 * ((lane >> 3) & 1);
                uint32_t t[4];
                ldmatrix_x4(t, bB + (uint32_t)(row * RS + kof) * 2);
                bfr[nb * 2][0] = t[0]; bfr[nb * 2][1] = t[1];
                bfr[nb * 2 + 1][0] = t[2]; bfr[nb * 2 + 1][1] = t[3];
            }
            #pragma unroll
            for (int mi = 0; mi < 4; mi++)
                #pragma unroll
                for (int ni = 0; ni < 4; ni++)
                    mma16816(acc[mi][ni], afr[mi], bfr[ni]);
        }
        __syncthreads();
    }

    // epilogue: bias + activation -> fp16 gate arrays
    const int gate  = n0 >> 10;
    const int hbase = n0 & (H_ - 1);
    __half* dst = (gate == 0) ? g_zh : ((gate == 1) ? g_fh : g_oh);

    #pragma unroll
    for (int mi = 0; mi < 4; mi++) {
        int r0 = m0 + wm * 64 + mi * 16 + (lane >> 2);
        #pragma unroll
        for (int ni = 0; ni < 4; ni++) {
            int c  = wn * 32 + ni * 8 + (lane & 3) * 2;
            float bx = __ldg(&bias[n0 + c]);
            float by = __ldg(&bias[n0 + c + 1]);
            float v0 = acc[mi][ni][0] + bx, v1 = acc[mi][ni][1] + by;
            float v2 = acc[mi][ni][2] + bx, v3 = acc[mi][ni][3] + by;
            if (gate == 0) { v0 = ftanh(v0); v1 = ftanh(v1); v2 = ftanh(v2); v3 = ftanh(v3); }
            else           { v0 = fsig(v0);  v1 = fsig(v1);  v2 = fsig(v2);  v3 = fsig(v3); }
            __half2 lo = __floats2half2_rn(v0, v1);
            __half2 hi = __floats2half2_rn(v2, v3);
            *(__half2*)&dst[(size_t)r0 * H_ + hbase + c]       = lo;
            *(__half2*)&dst[(size_t)(r0 + 8) * H_ + hbase + c] = hi;
        }
    }
}

// ---------------------------------------------------------------------------
// Chunked scan, SC=16.  chain = idx & (BH-1), c = idx >> 14.
// ---------------------------------------------------------------------------
__global__ __launch_bounds__(256) void scan_p1()
{
    const int idx   = blockIdx.x * 256 + threadIdx.x;   // over (SC-1)*BH
    const int chain = idx & (BH - 1);
    const int c     = idx >> 14;
    const int b = chain >> 10, h = chain & (H_ - 1);
    const size_t base = ((size_t)b * S_ + (size_t)c * CT) * H_ + h;

    constexpr int U = 8;
    float z[U], f[U];
    #pragma unroll
    for (int j = 0; j < U; j++) {
        size_t p = base + (size_t)j * H_;
        z[j] = __half2float(g_zh[p]); f[j] = __half2float(g_fh[p]);
    }
    float hh = 0.0f, P = 1.0f;
    for (int t = 0; t < CT; t += U) {
        float zn[U], fn[U];
        if (t + U < CT) {
            #pragma unroll
            for (int j = 0; j < U; j++) {
                size_t p = base + (size_t)(t + U + j) * H_;
                zn[j] = __half2float(g_zh[p]); fn[j] = __half2float(g_fh[p]);
            }
        }
        #pragma unroll
        for (int j = 0; j < U; j++) {
            hh = fmaf(f[j], z[j] - hh, hh);
            P *= (1.0f - f[j]);
        }
        #pragma unroll
        for (int j = 0; j < U; j++) { z[j] = zn[j]; f[j] = fn[j]; }
    }
    g_cA[idx] = hh;
    g_cP[idx] = P;
}

__global__ __launch_bounds__(256) void scan_p2()
{
    const int chain = blockIdx.x * 256 + threadIdx.x;
    float hs = 0.0f;
    g_hs[chain] = 0.0f;
    #pragma unroll
    for (int c = 0; c < SC - 1; c++) {
        hs = fmaf(g_cP[c * BH + chain], hs, g_cA[c * BH + chain]);
        g_hs[(c + 1) * BH + chain] = hs;
    }
}

__global__ __launch_bounds__(256) void scan_p3(float* __restrict__ out, int write_clast)
{
    const int idx   = blockIdx.x * 256 + threadIdx.x;   // over SC*BH
    const int chain = idx & (BH - 1);
    const int c     = idx >> 14;
    const int b = chain >> 10, h = chain & (H_ - 1);
    const size_t base = ((size_t)b * S_ + (size_t)c * CT) * H_ + h;

    constexpr int U = 8;
    float z[U], f[U], o[U];
    #pragma unroll
    for (int j = 0; j < U; j++) {
        size_t p = base + (size_t)j * H_;
        z[j] = __half2float(g_zh[p]); f[j] = __half2float(g_fh[p]);
        o[j] = __half2float(g_oh[p]);
    }
    float hh = g_hs[idx];
    for (int t = 0; t < CT; t += U) {
        float zn[U], fn[U], on[U];
        if (t + U < CT) {
            #pragma unroll
            for (int j = 0; j < U; j++) {
                size_t p = base + (size_t)(t + U + j) * H_;
                zn[j] = __half2float(g_zh[p]); fn[j] = __half2float(g_fh[p]);
                on[j] = __half2float(g_oh[p]);
            }
        }
        #pragma unroll
        for (int j = 0; j < U; j++) {
            hh = fmaf(f[j], z[j] - hh, hh);
            out[base + (size_t)(t + j) * H_] = o[j] * hh;
        }
        #pragma unroll
        for (int j = 0; j < U; j++) { z[j] = zn[j]; f[j] = fn[j]; o[j] = on[j]; }
    }
    if (write_clast && c == SC - 1)
        out[(size_t)M * H_ + chain] = hh;
}

// ---------------------------------------------------------------------------
extern "C" void kernel_launch(void* const* d_in, const int* in_sizes, int n_in,
                              void* d_out, int out_size)
{
    const float* inp  = (const float*)d_in[0];
    const float* Wt   = (const float*)d_in[1];
    const float* bias = (const float*)d_in[2];
    float* out = (float*)d_out;

    {
        int nA = M * K, nW = N3 * K;
        __half* dA; __half* dW;
        cudaGetSymbolAddress((void**)&dA, g_Ah);
        cudaGetSymbolAddress((void**)&dW, g_Wh);
        cvt_f2h<<<(nA / 8 + 255) / 256, 256>>>(inp, dA, nA);   // idx 0
        cvt_f2h<<<(nW / 8 + 255) / 256, 256>>>(Wt, dW, nW);    // idx 1
    }

    nop_a<<<1, 32>>>();                                        // idx 2

    // idx 3 == profiler capture slot
    cudaFuncSetAttribute(qrnn_gemm_h, cudaFuncAttributeMaxDynamicSharedMemorySize, SMEM_TOTAL);
    dim3 grid(N3 / BN, M / BM);                                // 24 x 256
    qrnn_gemm_h<<<grid, 256, SMEM_TOTAL>>>(bias);              // idx 3

    const long long need = (long long)M * H_ + (long long)BH;
    int write_clast = ((long long)out_size >= need) ? 1 : 0;

    scan_p1<<<(SC - 1) * BH / 256, 256>>>();                   // idx 4
    scan_p2<<<BH / 256, 256>>>();                              // idx 5
    scan_p3<<<SC * BH / 256, 256>>>(out, write_clast);         // idx 6
}